// round 1
// baseline (speedup 1.0000x reference)
#include <cuda_runtime.h>

// FineGrainedOpLSTMCell: h,c = LSTMCell(x, h_prev, c_prev; W*,U*,b*)
// B=131072, IN=128, H=128. Output = [h (B*H) ; c (B*H)] fp32.
//
// Round 1: exact fp32 fused GEMM+epilogue baseline.
//   GEMM view: P[B,512] = [x|h_prev][B,256] @ [W;U][256,512], cols = gate*128+j
//   CTA: BM=32 rows, all 512 cols. 256 threads; thread microtile = 8 rows x
//   (4 gates x 2 cols) = 64 fp32 accumulators -> epilogue fully thread-local.

namespace {
constexpr int Bsz  = 131072;
constexpr int IN   = 128;
constexpr int H    = 128;
constexpr int KTOT = 256;   // IN + H
constexpr int BM   = 32;
constexpr int BK   = 32;
constexpr int NCOL = 512;   // 4 gates * H

__global__ __launch_bounds__(256, 2)
void lstm_cell_kernel(const float* __restrict__ x,
                      const float* __restrict__ h_prev,
                      const float* __restrict__ c_prev,
                      const float* __restrict__ Wi, const float* __restrict__ Ui, const float* __restrict__ bi,
                      const float* __restrict__ Wf, const float* __restrict__ Uf, const float* __restrict__ bf,
                      const float* __restrict__ Wg, const float* __restrict__ Ug, const float* __restrict__ bg,
                      const float* __restrict__ Wo, const float* __restrict__ Uo, const float* __restrict__ bo,
                      float* __restrict__ out)
{
    extern __shared__ float smem[];
    float* xs = smem;                 // BM x BK  (1024 floats)
    float* ws = smem + BM * BK;       // BK x NCOL (16384 floats)

    const int tid = threadIdx.x;
    const int jg  = tid & 63;         // column-pair group: cols j0=2*jg, j0+1 within each gate
    const int rg  = tid >> 6;         // row group 0..3 (8 rows each)
    const int gr  = blockIdx.x * BM;  // global row base

    // --- weight-stage index algebra (warp-uniform gate selection) ---
    // float4 id f4 = i*256 + tid  (i in 0..15), row = f4>>7, col4 = (f4&127)*4.
    // => gate  g  = (tid>>5)&3   (constant per thread, uniform per warp)
    //    jc       = (tid&31)*4   (constant per thread)
    //    row      = 2*i + (tid>>7)
    const int wg_gate = (tid >> 5) & 3;
    const int wg_jc   = (tid & 31) * 4;
    const int wg_rb   = tid >> 7;

    const float* Wsel = (wg_gate == 0) ? Wi : (wg_gate == 1) ? Wf : (wg_gate == 2) ? Wg : Wo;
    const float* Usel = (wg_gate == 0) ? Ui : (wg_gate == 1) ? Uf : (wg_gate == 2) ? Ug : Uo;

    float acc[4][8][2];
    #pragma unroll
    for (int g = 0; g < 4; ++g)
        #pragma unroll
        for (int r = 0; r < 8; ++r) { acc[g][r][0] = 0.f; acc[g][r][1] = 0.f; }

    for (int kc = 0; kc < KTOT / BK; ++kc) {
        const int  kb    = kc * BK;
        const bool phaseX = (kb < IN);
        const float* amat = phaseX ? x : h_prev;
        const float* wmat = phaseX ? Wsel : Usel;
        const int  koff   = phaseX ? kb : (kb - IN);

        // stage A tile: 32x32 floats, one float4 per thread
        {
            const int r  = tid >> 3;         // 0..31
            const int c4 = (tid & 7) * 4;    // 0,4,..,28
            float4 v = *(const float4*)&amat[(size_t)(gr + r) * IN + (koff + c4)];
            *(float4*)&xs[r * BK + c4] = v;
        }
        // stage weight tile: 32 x 512 floats, 16 float4 per thread
        #pragma unroll
        for (int i = 0; i < 16; ++i) {
            const int row = 2 * i + wg_rb;
            float4 v = *(const float4*)&wmat[(size_t)(koff + row) * H + wg_jc];
            *(float4*)&ws[row * NCOL + wg_gate * H + wg_jc] = v;
        }
        __syncthreads();

        #pragma unroll 4
        for (int kk = 0; kk < BK; ++kk) {
            float a[8];
            #pragma unroll
            for (int r = 0; r < 8; ++r)
                a[r] = xs[(rg * 8 + r) * BK + kk];   // warp-broadcast
            float2 b[4];
            #pragma unroll
            for (int g = 0; g < 4; ++g)
                b[g] = *(const float2*)&ws[kk * NCOL + g * H + 2 * jg];
            #pragma unroll
            for (int g = 0; g < 4; ++g)
                #pragma unroll
                for (int r = 0; r < 8; ++r) {
                    acc[g][r][0] = fmaf(a[r], b[g].x, acc[g][r][0]);
                    acc[g][r][1] = fmaf(a[r], b[g].y, acc[g][r][1]);
                }
        }
        __syncthreads();
    }

    // ---------------- epilogue (thread-local, all 4 gates present) ----------
    const int j0 = 2 * jg;
    const float2 bI = *(const float2*)&bi[j0];
    const float2 bF = *(const float2*)&bf[j0];
    const float2 bG = *(const float2*)&bg[j0];
    const float2 bO = *(const float2*)&bo[j0];

    float* out_h = out;
    float* out_c = out + (size_t)Bsz * H;

    #pragma unroll
    for (int r = 0; r < 8; ++r) {
        const size_t row = (size_t)gr + rg * 8 + r;
        const float2 cp = *(const float2*)&c_prev[row * H + j0];
        float2 hv, cv;
        #pragma unroll
        for (int jj = 0; jj < 2; ++jj) {
            const float pi = acc[0][r][jj] + (jj ? bI.y : bI.x);
            const float pf = acc[1][r][jj] + (jj ? bF.y : bF.x);
            const float pg = acc[2][r][jj] + (jj ? bG.y : bG.x);
            const float po = acc[3][r][jj] + (jj ? bO.y : bO.x);
            const float ig = 1.f / (1.f + expf(-pi));
            const float fg = 1.f / (1.f + expf(-pf));
            const float og = 1.f / (1.f + expf(-po));
            const float gg = tanhf(pg);
            const float cpv = jj ? cp.y : cp.x;
            const float c = fg * cpv + ig * gg;
            const float h = og * tanhf(c);
            if (jj) { cv.y = c; hv.y = h; } else { cv.x = c; hv.x = h; }
        }
        *(float2*)&out_h[row * H + j0] = hv;
        *(float2*)&out_c[row * H + j0] = cv;
    }
}
} // namespace

extern "C" void kernel_launch(void* const* d_in, const int* in_sizes, int n_in,
                              void* d_out, int out_size)
{
    (void)in_sizes; (void)n_in; (void)out_size;
    const float* x      = (const float*)d_in[0];
    const float* h_prev = (const float*)d_in[1];
    const float* c_prev = (const float*)d_in[2];
    const float* Wi = (const float*)d_in[3];
    const float* Ui = (const float*)d_in[4];
    const float* bi = (const float*)d_in[5];
    const float* Wf = (const float*)d_in[6];
    const float* Uf = (const float*)d_in[7];
    const float* bf = (const float*)d_in[8];
    const float* Wg = (const float*)d_in[9];
    const float* Ug = (const float*)d_in[10];
    const float* bg = (const float*)d_in[11];
    const float* Wo = (const float*)d_in[12];
    const float* Uo = (const float*)d_in[13];
    const float* bo = (const float*)d_in[14];
    float* out = (float*)d_out;

    const int smem_bytes = (BM * BK + BK * NCOL) * (int)sizeof(float);  // 69632
    cudaFuncSetAttribute(lstm_cell_kernel,
                         cudaFuncAttributeMaxDynamicSharedMemorySize, smem_bytes);

    dim3 grid(Bsz / BM);   // 4096
    dim3 block(256);
    lstm_cell_kernel<<<grid, block, smem_bytes>>>(
        x, h_prev, c_prev, Wi, Ui, bi, Wf, Uf, bf, Wg, Ug, bg, Wo, Uo, bo, out);
}

// round 4
// speedup vs baseline: 4.5212x; 4.5212x over previous
#include <cuda_runtime.h>
#include <cuda_fp16.h>
#include <cstdint>

// LSTMCell via mma.sync (HMMA) fp16 GEMM, fp32 accum, fused epilogue.
//   P[B,512] = [x|h][B,256] @ B'[512,256]^T,  n = gate*128 + j
// Persistent kernel: CTA keeps its B tile (fixed j-block) in smem for all tiles.

namespace {

constexpr int Bsz   = 131072;
constexpr int HH    = 128;
constexpr int NWORK = 4096;          // 1024 mtiles * 4 jblocks

// fp16 weights, K-major: g_B[n][k], n = gate*128 + j, k = 0..255
__device__ __align__(16) __half g_B[512 * 256];

__device__ __forceinline__ uint32_t s2u(const void* p) {
    uint32_t a;
    asm("{ .reg .u64 t; cvta.to.shared.u64 t, %1; cvt.u32.u64 %0, t; }" : "=r"(a) : "l"(p));
    return a;
}
__device__ __forceinline__ void mma16816(float* d, uint32_t a0, uint32_t a1, uint32_t a2, uint32_t a3,
                                         uint32_t b0, uint32_t b1) {
    asm volatile("mma.sync.aligned.m16n8k16.row.col.f32.f16.f16.f32 "
                 "{%0,%1,%2,%3},{%4,%5,%6,%7},{%8,%9},{%0,%1,%2,%3};"
                 : "+f"(d[0]), "+f"(d[1]), "+f"(d[2]), "+f"(d[3])
                 : "r"(a0), "r"(a1), "r"(a2), "r"(a3), "r"(b0), "r"(b1));
}
#define LDSM4(r0, r1, r2, r3, addr) \
    asm volatile("ldmatrix.sync.aligned.m8n8.x4.shared.b16 {%0,%1,%2,%3}, [%4];" \
                 : "=r"(r0), "=r"(r1), "=r"(r2), "=r"(r3) : "r"(addr) : "memory")

// ---------------- prep: weights fp32 -> fp16, transposed to [n][k] ----------------
__global__ void prep_w(const float* __restrict__ Wi, const float* __restrict__ Ui,
                       const float* __restrict__ Wf, const float* __restrict__ Uf,
                       const float* __restrict__ Wg, const float* __restrict__ Ug,
                       const float* __restrict__ Wo, const float* __restrict__ Uo) {
    int t = blockIdx.x * 256 + threadIdx.x;   // 8192 threads
    int n = t >> 4;
    int k0 = (t & 15) * 16;
    int g = n >> 7, j = n & 127;
    const float* W = (g == 0) ? Wi : (g == 1) ? Wf : (g == 2) ? Wg : Wo;
    const float* U = (g == 0) ? Ui : (g == 1) ? Uf : (g == 2) ? Ug : Uo;
    __half tmp[16];
    #pragma unroll
    for (int kk = 0; kk < 16; ++kk) {
        int k = k0 + kk;
        float v = (k < 128) ? W[k * 128 + j] : U[(k - 128) * 128 + j];
        tmp[kk] = __float2half_rn(v);
    }
    reinterpret_cast<uint4*>(&g_B[n * 256 + k0])[0] = reinterpret_cast<uint4*>(tmp)[0];
    reinterpret_cast<uint4*>(&g_B[n * 256 + k0])[1] = reinterpret_cast<uint4*>(tmp)[1];
}

// ---------------- main ----------------
// smem (bytes): A0 @0 (67584), A1 @67584, B @135168 (67584), bias @202752 (2048)
constexpr int SM_A1   = 67584;     // 128 rows * 264 halves * 2B
constexpr int SM_B    = 135168;
constexpr int SM_BIAS = 202752;
constexpr int SM_TOT  = 204800;

__global__ __launch_bounds__(512)
void lstm_main(const float* __restrict__ x, const float* __restrict__ hp,
               const float* __restrict__ cp,
               const float* __restrict__ bi, const float* __restrict__ bf,
               const float* __restrict__ bg, const float* __restrict__ bo,
               float* __restrict__ out, int grid)
{
    extern __shared__ __align__(16) unsigned char smem[];
    const uint32_t sbase = s2u(smem);
    const uint32_t bs_u  = sbase + SM_B;
    float* bsm = (float*)(smem + SM_BIAS);

    const int tid = threadIdx.x, lane = tid & 31, wid = tid >> 5;
    const int jb = blockIdx.x & 3;

    // biases -> smem
    {
        int g = tid >> 7, j = tid & 127;
        const float* bb = (g == 0) ? bi : (g == 1) ? bf : (g == 2) ? bg : bo;
        bsm[tid] = bb[j];
    }

    // B tile (fixed for this CTA): 128 n-rows (4 gates x 32 j) x 256 k fp16
    #pragma unroll
    for (int i = 0; i < 8; ++i) {
        int c  = i * 512 + tid;
        int nl = c >> 5, seg = c & 31;
        int ng = (nl >> 5) * 128 + jb * 32 + (nl & 31);
        uint32_t dst = bs_u + (uint32_t)(nl * 528 + seg * 16);
        const void* src = (const char*)g_B + (size_t)ng * 512 + (size_t)seg * 16;
        asm volatile("cp.async.cg.shared.global [%0], [%1], 16;" :: "r"(dst), "l"(src) : "memory");
    }
    asm volatile("cp.async.commit_group;" ::: "memory");

    // A prefetch registers: full 128x256 fp32 tile across 512 threads
    //   64 threads per row-slice (tid&63 -> k column), 8 row groups (tid>>6),
    //   16 rows per thread (r = i*8 + rsub) -> 16 float4 per thread.
    const int c4   = (tid & 63) * 4;  // fp32 k-col 0..252
    const int rsub = tid >> 6;        // 0..7
    float4 pf[16];
    auto loadA = [&](int mtile) {
        #pragma unroll
        for (int i = 0; i < 16; ++i) {
            int r = i * 8 + rsub;
            size_t rg = (size_t)mtile * 128 + r;
            const float* src = (c4 < 128) ? (x + rg * 128 + c4) : (hp + rg * 128 + (c4 - 128));
            pf[i] = *(const float4*)src;
        }
    };
    int wi = blockIdx.x;
    loadA(wi >> 2);

    asm volatile("cp.async.wait_group 0;" ::: "memory");
    __syncthreads();   // B + bias visible

    // warp tiling: wm in 0..7 -> rows wm*16 ; wn in 0..1 -> j-half wn*16
    const int wm = wid & 7, wn = wid >> 3;
    const uint32_t aoff = (uint32_t)(((wm * 16 + (lane & 15)) * 264 + (lane >> 4) * 8) * 2);
    uint32_t bAddr[4];
    #pragma unroll
    for (int g = 0; g < 4; ++g)
        bAddr[g] = bs_u + (uint32_t)(((g * 32 + wn * 16 + (lane & 15)) * 264 + (lane >> 4) * 8) * 2);

    float* out_h = out;
    float* out_c = out + (size_t)Bsz * HH;

    for (int it = 0; wi < NWORK; wi += grid, ++it) {
        const int mtile = wi >> 2;
        const uint32_t abase = sbase + (uint32_t)((it & 1) * SM_A1);

        // convert + store this tile's A (from prefetched regs)
        #pragma unroll
        for (int i = 0; i < 16; ++i) {
            int r = i * 8 + rsub;
            __half2 h0 = __floats2half2_rn(pf[i].x, pf[i].y);
            __half2 h1 = __floats2half2_rn(pf[i].z, pf[i].w);
            uint32_t a = abase + (uint32_t)((r * 264 + c4) * 2);
            asm volatile("st.shared.v2.b32 [%0], {%1,%2};"
                         :: "r"(a), "r"(*(uint32_t*)&h0), "r"(*(uint32_t*)&h1) : "memory");
        }
        __syncthreads();

        // prefetch next tile's A (hides DRAM under MMA)
        int win = wi + grid;
        if (win < NWORK) loadA(win >> 2);

        // prefetch c_prev for epilogue
        const int r0  = mtile * 128 + wm * 16 + (lane >> 2);
        const int jgl = jb * 32 + wn * 16 + 2 * (lane & 3);
        float2 cpv[2][2];
        #pragma unroll
        for (int jt = 0; jt < 2; ++jt)
            #pragma unroll
            for (int rr = 0; rr < 2; ++rr)
                cpv[jt][rr] = *(const float2*)&cp[(size_t)(r0 + rr * 8) * HH + jgl + jt * 8];

        // ---- MMA mainloop: 16 k-steps, 8 HMMA each ----
        float acc[4][2][4];
        #pragma unroll
        for (int g = 0; g < 4; ++g)
            #pragma unroll
            for (int jt = 0; jt < 2; ++jt)
                #pragma unroll
                for (int e = 0; e < 4; ++e) acc[g][jt][e] = 0.f;

        const uint32_t aA = abase + aoff;
        #pragma unroll
        for (int ks = 0; ks < 16; ++ks) {
            uint32_t a0, a1, a2, a3;
            LDSM4(a0, a1, a2, a3, aA + ks * 32);
            #pragma unroll
            for (int g = 0; g < 4; ++g) {
                uint32_t b0, b1, b2, b3;
                LDSM4(b0, b1, b2, b3, bAddr[g] + ks * 32);
                mma16816(acc[g][0], a0, a1, a2, a3, b0, b2);
                mma16816(acc[g][1], a0, a1, a2, a3, b1, b3);
            }
        }

        // ---- fused epilogue ----
        #pragma unroll
        for (int jt = 0; jt < 2; ++jt) {
            #pragma unroll
            for (int rr = 0; rr < 2; ++rr) {
                float2 hv, cv;
                #pragma unroll
                for (int e = 0; e < 2; ++e) {
                    const int jcol = jgl + jt * 8 + e;
                    const float pi_ = acc[0][jt][rr * 2 + e] + bsm[jcol];
                    const float pf_ = acc[1][jt][rr * 2 + e] + bsm[128 + jcol];
                    const float pg_ = acc[2][jt][rr * 2 + e] + bsm[256 + jcol];
                    const float po_ = acc[3][jt][rr * 2 + e] + bsm[384 + jcol];
                    const float ig = __fdividef(1.f, 1.f + __expf(-pi_));
                    const float fg = __fdividef(1.f, 1.f + __expf(-pf_));
                    const float og = __fdividef(1.f, 1.f + __expf(-po_));
                    const float gg = 1.f - __fdividef(2.f, __expf(2.f * pg_) + 1.f);
                    const float cpe = e ? cpv[jt][rr].y : cpv[jt][rr].x;
                    const float cn = fg * cpe + ig * gg;
                    const float hn = og * (1.f - __fdividef(2.f, __expf(2.f * cn) + 1.f));
                    if (e) { cv.y = cn; hv.y = hn; } else { cv.x = cn; hv.x = hn; }
                }
                const size_t o = (size_t)(r0 + rr * 8) * HH + jgl + jt * 8;
                *(float2*)&out_h[o] = hv;
                *(float2*)&out_c[o] = cv;
            }
        }
    }
}

} // namespace

extern "C" void kernel_launch(void* const* d_in, const int* in_sizes, int n_in,
                              void* d_out, int out_size)
{
    (void)in_sizes; (void)n_in; (void)out_size;
    const float* x      = (const float*)d_in[0];
    const float* h_prev = (const float*)d_in[1];
    const float* c_prev = (const float*)d_in[2];
    const float* Wi = (const float*)d_in[3];
    const float* Ui = (const float*)d_in[4];
    const float* bi = (const float*)d_in[5];
    const float* Wf = (const float*)d_in[6];
    const float* Uf = (const float*)d_in[7];
    const float* bf = (const float*)d_in[8];
    const float* Wg = (const float*)d_in[9];
    const float* Ug = (const float*)d_in[10];
    const float* bg = (const float*)d_in[11];
    const float* Wo = (const float*)d_in[12];
    const float* Uo = (const float*)d_in[13];
    const float* bo = (const float*)d_in[14];
    float* out = (float*)d_out;

    int sms = 148;
    cudaDeviceGetAttribute(&sms, cudaDevAttrMultiProcessorCount, 0);
    if (sms < 4 || sms > 1024) sms = 148;
    const int grid = (sms / 4) * 4;   // jb = bid&3 stays fixed per CTA

    cudaFuncSetAttribute(lstm_main, cudaFuncAttributeMaxDynamicSharedMemorySize, SM_TOT);

    prep_w<<<32, 256>>>(Wi, Ui, Wf, Uf, Wg, Ug, Wo, Uo);
    lstm_main<<<grid, 512, SM_TOT>>>(x, h_prev, c_prev, bi, bf, bg, bo, out, grid);
}

// round 5
// speedup vs baseline: 4.7199x; 1.0439x over previous
#include <cuda_runtime.h>
#include <cuda_fp16.h>
#include <cstdint>

// LSTMCell via mma.sync (HMMA) fp16 GEMM, fp32 accum, fused epilogue.
//   P[B,512] = [x|h][B,256] @ B'[512,256]^T,  n = gate*128 + j
// Persistent kernel; warp tile 32Mx32N (4 gates x 8 j), gather-ldmatrix for B.

namespace {

constexpr int Bsz   = 131072;
constexpr int HH    = 128;
constexpr int NWORK = 4096;          // 1024 mtiles * 4 jblocks

// fp16 weights, K-major: g_B[n][k], n = gate*128 + j, k = 0..255
__device__ __align__(16) __half g_B[512 * 256];

__device__ __forceinline__ uint32_t s2u(const void* p) {
    uint32_t a;
    asm("{ .reg .u64 t; cvta.to.shared.u64 t, %1; cvt.u32.u64 %0, t; }" : "=r"(a) : "l"(p));
    return a;
}
__device__ __forceinline__ float tanh_fast(float v) {
    float r;
    asm("tanh.approx.f32 %0, %1;" : "=f"(r) : "f"(v));
    return r;
}
__device__ __forceinline__ float sig_fast(float v) {
    return fmaf(tanh_fast(0.5f * v), 0.5f, 0.5f);
}
__device__ __forceinline__ void mma16816(float* d, uint32_t a0, uint32_t a1, uint32_t a2, uint32_t a3,
                                         uint32_t b0, uint32_t b1) {
    asm volatile("mma.sync.aligned.m16n8k16.row.col.f32.f16.f16.f32 "
                 "{%0,%1,%2,%3},{%4,%5,%6,%7},{%8,%9},{%0,%1,%2,%3};"
                 : "+f"(d[0]), "+f"(d[1]), "+f"(d[2]), "+f"(d[3])
                 : "r"(a0), "r"(a1), "r"(a2), "r"(a3), "r"(b0), "r"(b1));
}
#define LDSM4(r0, r1, r2, r3, addr) \
    asm volatile("ldmatrix.sync.aligned.m8n8.x4.shared.b16 {%0,%1,%2,%3}, [%4];" \
                 : "=r"(r0), "=r"(r1), "=r"(r2), "=r"(r3) : "r"(addr) : "memory")

// ---------------- prep: weights fp32 -> fp16, transposed to [n][k] ----------------
__global__ void prep_w(const float* __restrict__ Wi, const float* __restrict__ Ui,
                       const float* __restrict__ Wf, const float* __restrict__ Uf,
                       const float* __restrict__ Wg, const float* __restrict__ Ug,
                       const float* __restrict__ Wo, const float* __restrict__ Uo) {
    int t = blockIdx.x * 256 + threadIdx.x;   // 8192 threads
    int n = t >> 4;
    int k0 = (t & 15) * 16;
    int g = n >> 7, j = n & 127;
    const float* W = (g == 0) ? Wi : (g == 1) ? Wf : (g == 2) ? Wg : Wo;
    const float* U = (g == 0) ? Ui : (g == 1) ? Uf : (g == 2) ? Ug : Uo;
    __half tmp[16];
    #pragma unroll
    for (int kk = 0; kk < 16; ++kk) {
        int k = k0 + kk;
        float v = (k < 128) ? W[k * 128 + j] : U[(k - 128) * 128 + j];
        tmp[kk] = __float2half_rn(v);
    }
    reinterpret_cast<uint4*>(&g_B[n * 256 + k0])[0] = reinterpret_cast<uint4*>(tmp)[0];
    reinterpret_cast<uint4*>(&g_B[n * 256 + k0])[1] = reinterpret_cast<uint4*>(tmp)[1];
}

// ---------------- main ----------------
// smem (bytes): A0 @0 (67584), A1 @67584, B @135168 (67584)
constexpr int SM_A1 = 67584;     // 128 rows * 264 halves * 2B
constexpr int SM_B  = 135168;
constexpr int SM_TOT = 202752;

__global__ __launch_bounds__(512)
void lstm_main(const float* __restrict__ x, const float* __restrict__ hp,
               const float* __restrict__ cp,
               const float* __restrict__ bi, const float* __restrict__ bf,
               const float* __restrict__ bg, const float* __restrict__ bo,
               float* __restrict__ out, int grid)
{
    extern __shared__ __align__(16) unsigned char smem[];
    const uint32_t sbase = s2u(smem);
    const uint32_t bs_u  = sbase + SM_B;

    const int tid = threadIdx.x, lane = tid & 31, wid = tid >> 5;
    const int jb = blockIdx.x & 3;

    // B tile (fixed for this CTA): 128 n-rows (4 gates x 32 j) x 256 k fp16
    #pragma unroll
    for (int i = 0; i < 8; ++i) {
        int c  = i * 512 + tid;
        int nl = c >> 5, seg = c & 31;
        int ng = (nl >> 5) * 128 + jb * 32 + (nl & 31);
        uint32_t dst = bs_u + (uint32_t)(nl * 528 + seg * 16);
        const void* src = (const char*)g_B + (size_t)ng * 512 + (size_t)seg * 16;
        asm volatile("cp.async.cg.shared.global [%0], [%1], 16;" :: "r"(dst), "l"(src) : "memory");
    }
    asm volatile("cp.async.commit_group;" ::: "memory");

    // A prefetch registers: full 128x256 fp32 tile across 512 threads
    const int c4   = (tid & 63) * 4;  // fp32 k-col 0..252
    const int rsub = tid >> 6;        // 0..7
    float4 pf[16];
    auto loadA = [&](int mtile) {
        #pragma unroll
        for (int i = 0; i < 16; ++i) {
            int r = i * 8 + rsub;
            size_t rg = (size_t)mtile * 128 + r;
            const float* src = (c4 < 128) ? (x + rg * 128 + c4) : (hp + rg * 128 + (c4 - 128));
            pf[i] = *(const float4*)src;
        }
    };
    int wi = blockIdx.x;
    loadA(wi >> 2);

    // warp tiling: wm in 0..3 -> rows wm*32 (2 x m16 frags); wn in 0..3 -> j-slice wn*8
    const int wm = wid & 3, wn = wid >> 2;

    // A ldmatrix offsets (relative to abase) for the two m16 fragments
    const uint32_t aoff0 = (uint32_t)(((wm * 32 +      (lane & 15)) * 264 + (lane >> 4) * 8) * 2);
    const uint32_t aoff1 = (uint32_t)(((wm * 32 + 16 + (lane & 15)) * 264 + (lane >> 4) * 8) * 2);
    // B gather ldmatrix: matrix g (= lane>>3) row (lane&7): n_local = g*32 + wn*8 + (lane&7)
    const uint32_t bAddr = bs_u + (uint32_t)(((lane >> 3) * 32 + wn * 8 + (lane & 7)) * 528);

    // biases -> registers (j-cols are loop-invariant per thread)
    const int jgl = jb * 32 + wn * 8 + 2 * (lane & 3);    // global j (2 cols: jgl, jgl+1)
    const float2 bI = *(const float2*)&bi[jgl];
    const float2 bF = *(const float2*)&bf[jgl];
    const float2 bG = *(const float2*)&bg[jgl];
    const float2 bO = *(const float2*)&bo[jgl];

    asm volatile("cp.async.wait_group 0;" ::: "memory");
    __syncthreads();   // B visible

    float* out_h = out;
    float* out_c = out + (size_t)Bsz * HH;

    for (int it = 0; wi < NWORK; wi += grid, ++it) {
        const int mtile = wi >> 2;
        const uint32_t abase = sbase + (uint32_t)((it & 1) * SM_A1);

        // convert + store this tile's A (from prefetched regs)
        #pragma unroll
        for (int i = 0; i < 16; ++i) {
            int r = i * 8 + rsub;
            __half2 h0 = __floats2half2_rn(pf[i].x, pf[i].y);
            __half2 h1 = __floats2half2_rn(pf[i].z, pf[i].w);
            uint32_t a = abase + (uint32_t)((r * 264 + c4) * 2);
            asm volatile("st.shared.v2.b32 [%0], {%1,%2};"
                         :: "r"(a), "r"(*(uint32_t*)&h0), "r"(*(uint32_t*)&h1) : "memory");
        }
        __syncthreads();

        // prefetch next tile's A (hides DRAM under MMA)
        int win = wi + grid;
        if (win < NWORK) loadA(win >> 2);

        // prefetch c_prev for epilogue: rows per mf frag
        const int rbase = mtile * 128 + wm * 32 + (lane >> 2);
        float2 cpv[2][2];
        #pragma unroll
        for (int mf = 0; mf < 2; ++mf)
            #pragma unroll
            for (int rr = 0; rr < 2; ++rr)
                cpv[mf][rr] = *(const float2*)&cp[(size_t)(rbase + mf * 16 + rr * 8) * HH + jgl];

        // ---- MMA mainloop: 16 k-steps; per ks: 2 A-LDSM4 + 2 B-LDSM4, 8 HMMA ----
        float acc[2][4][4];   // [mfrag][gate][elem]
        #pragma unroll
        for (int mf = 0; mf < 2; ++mf)
            #pragma unroll
            for (int g = 0; g < 4; ++g)
                #pragma unroll
                for (int e = 0; e < 4; ++e) acc[mf][g][e] = 0.f;

        #pragma unroll
        for (int ks = 0; ks < 16; ++ks) {
            uint32_t a0, a1, a2, a3, a4, a5, a6, a7;
            LDSM4(a0, a1, a2, a3, abase + aoff0 + ks * 32);
            LDSM4(a4, a5, a6, a7, abase + aoff1 + ks * 32);
            uint32_t p0, p1, p2, p3, q0, q1, q2, q3;
            LDSM4(p0, p1, p2, p3, bAddr + ks * 32);        // gates 0..3, k 0-7
            LDSM4(q0, q1, q2, q3, bAddr + ks * 32 + 16);   // gates 0..3, k 8-15
            mma16816(acc[0][0], a0, a1, a2, a3, p0, q0);
            mma16816(acc[1][0], a4, a5, a6, a7, p0, q0);
            mma16816(acc[0][1], a0, a1, a2, a3, p1, q1);
            mma16816(acc[1][1], a4, a5, a6, a7, p1, q1);
            mma16816(acc[0][2], a0, a1, a2, a3, p2, q2);
            mma16816(acc[1][2], a4, a5, a6, a7, p2, q2);
            mma16816(acc[0][3], a0, a1, a2, a3, p3, q3);
            mma16816(acc[1][3], a4, a5, a6, a7, p3, q3);
        }

        // ---- fused epilogue (tanh.approx: 5 MUFU / element) ----
        #pragma unroll
        for (int mf = 0; mf < 2; ++mf) {
            #pragma unroll
            for (int rr = 0; rr < 2; ++rr) {
                float2 hv, cv;
                #pragma unroll
                for (int e = 0; e < 2; ++e) {
                    const float pi_ = acc[mf][0][rr * 2 + e] + (e ? bI.y : bI.x);
                    const float pf_ = acc[mf][1][rr * 2 + e] + (e ? bF.y : bF.x);
                    const float pg_ = acc[mf][2][rr * 2 + e] + (e ? bG.y : bG.x);
                    const float po_ = acc[mf][3][rr * 2 + e] + (e ? bO.y : bO.x);
                    const float ig = sig_fast(pi_);
                    const float fg = sig_fast(pf_);
                    const float og = sig_fast(po_);
                    const float gg = tanh_fast(pg_);
                    const float cpe = e ? cpv[mf][rr].y : cpv[mf][rr].x;
                    const float cn = fg * cpe + ig * gg;
                    const float hn = og * tanh_fast(cn);
                    if (e) { cv.y = cn; hv.y = hn; } else { cv.x = cn; hv.x = hn; }
                }
                const size_t o = (size_t)(rbase + mf * 16 + rr * 8) * HH + jgl;
                *(float2*)&out_h[o] = hv;
                *(float2*)&out_c[o] = cv;
            }
        }
    }
}

} // namespace

extern "C" void kernel_launch(void* const* d_in, const int* in_sizes, int n_in,
                              void* d_out, int out_size)
{
    (void)in_sizes; (void)n_in; (void)out_size;
    const float* x      = (const float*)d_in[0];
    const float* h_prev = (const float*)d_in[1];
    const float* c_prev = (const float*)d_in[2];
    const float* Wi = (const float*)d_in[3];
    const float* Ui = (const float*)d_in[4];
    const float* bi = (const float*)d_in[5];
    const float* Wf = (const float*)d_in[6];
    const float* Uf = (const float*)d_in[7];
    const float* bf = (const float*)d_in[8];
    const float* Wg = (const float*)d_in[9];
    const float* Ug = (const float*)d_in[10];
    const float* bg = (const float*)d_in[11];
    const float* Wo = (const float*)d_in[12];
    const float* Uo = (const float*)d_in[13];
    const float* bo = (const float*)d_in[14];
    float* out = (float*)d_out;

    int sms = 148;
    cudaDeviceGetAttribute(&sms, cudaDevAttrMultiProcessorCount, 0);
    if (sms < 4 || sms > 1024) sms = 148;
    const int grid = (sms / 4) * 4;   // jb = bid&3 stays fixed per CTA

    cudaFuncSetAttribute(lstm_main, cudaFuncAttributeMaxDynamicSharedMemorySize, SM_TOT);

    prep_w<<<32, 256>>>(Wi, Ui, Wf, Uf, Wg, Ug, Wo, Uo);
    lstm_main<<<grid, 512, SM_TOT>>>(x, h_prev, c_prev, bi, bf, bg, bo, out, grid);
}